// round 9
// baseline (speedup 1.0000x reference)
#include <cuda_runtime.h>
#include <cuda_fp16.h>

#define V_N 100000
#define E_N 1600000
#define SCAN_B 391   // ceil(V_N/256)

typedef unsigned long long u64;

// ---------------- static device scratch (no allocations allowed) ----------------
__device__ __half g_A[(size_t)E_N * 64];   // 204.8 MB, dst-sorted slot layout: slot-major, 64 halves/edge
__device__ float  g_P[V_N * 64];           // feat @ Wxi[:, 0:64]^T
__device__ float  g_Q[V_N * 64];           // feat @ Wxi[:, 64:128]^T
__device__ float  g_R[V_N * 8];            // tanh(feat @ W_rou^T + b_rou)
__device__ float  g_B2[V_N * 8];           // per-step init: cnt[n] * R[n-1]
__device__ float  g_HA[V_N * 8];
__device__ float  g_HB[V_N * 8];
__device__ int    g_src[E_N];              // X_Node - 1
__device__ int    g_dst[E_N];              // raw X_Neis (1-indexed segment id)
__device__ int    g_cnt[V_N];
__device__ int    g_cursor[V_N];
__device__ int    g_off[V_N + 1];          // CSR offsets by dst segment
__device__ int    g_bsum[512];
__device__ int    g_bpre[512];
__device__ int    g_slot[E_N];             // edge -> sorted slot (-1 = dropped)
__device__ int    g_slotsrc[E_N];          // sorted slot -> src node
__device__ float  g_logits[V_N];
__device__ int    g_is64;
__device__ int    g_maxI;
__device__ double g_sumExp;
__device__ double g_wsum[8];

// ---------------- helpers ----------------
__device__ __forceinline__ float tanh_fast(float x) {
    x = fminf(fmaxf(x, -9.f), 9.f);
    float t = __expf(2.f * x);
    return __fdividef(t - 1.f, t + 1.f);
}

__device__ __forceinline__ void red_v4(float* p, float a, float b, float c, float d) {
    asm volatile("red.global.add.v4.f32 [%0], {%1, %2, %3, %4};"
                 :: "l"(p), "f"(a), "f"(b), "f"(c), "f"(d) : "memory");
}

// packed fp32x2 FMA (Blackwell; .rn lanewise, bit-identical to scalar FFMA)
__device__ __forceinline__ void fma2(u64& d, u64 a, u64 b) {
    asm("fma.rn.f32x2 %0, %1, %2, %0;" : "+l"(d) : "l"(a), "l"(b));
}
__device__ __forceinline__ u64 pack2(float f) {
    u64 r;
    asm("mov.b64 %0, {%1, %1};" : "=l"(r) : "r"(__float_as_uint(f)));
    return r;
}

// ---------------- kernels ----------------
__global__ void k_zero() {
    int i = blockIdx.x * blockDim.x + threadIdx.x;
    if (i < V_N) { g_cnt[i] = 0; g_cursor[i] = 0; }
    if (i == 0) {
        g_maxI = (int)0x80000000;
        g_sumExp = 0.0;
        #pragma unroll
        for (int s = 0; s < 8; s++) g_wsum[s] = 0.0;
    }
}

// Detect int64 vs int32 index arrays: values are in [1, V] (never 0), so the
// high dword of an int64 little-endian pair is 0 iff the data is int64.
__global__ void k_detect(const void* xn) {
    if (blockIdx.x == 0 && threadIdx.x == 0) {
        const int2* p = (const int2*)xn;
        int ok = 1;
        for (int k = 0; k < 64; k++) if (p[k].y != 0) ok = 0;
        g_is64 = ok;
    }
}

__global__ void __launch_bounds__(256) k_prep(const void* xn, const void* xs) {
    int e = blockIdx.x * 256 + threadIdx.x;
    if (e >= E_N) return;
    long long a, b;
    if (g_is64) {
        a = ((const long long*)xn)[e];
        b = ((const long long*)xs)[e];
    } else {
        a = ((const int*)xn)[e];
        b = ((const int*)xs)[e];
    }
    g_src[e] = (int)(a - 1);
    int d = (int)b;
    g_dst[e] = d;
    if (d < V_N) atomicAdd(&g_cnt[d], 1);   // segment id == V is dropped
}

// ---- CSR build: 3-kernel exclusive scan of g_cnt + slot assignment ----
__global__ void __launch_bounds__(256) k_scan1() {
    __shared__ int sh[256];
    int idx = blockIdx.x * 256 + threadIdx.x;
    sh[threadIdx.x] = (idx < V_N) ? g_cnt[idx] : 0;
    __syncthreads();
    for (int s = 128; s > 0; s >>= 1) {
        if (threadIdx.x < s) sh[threadIdx.x] += sh[threadIdx.x + s];
        __syncthreads();
    }
    if (threadIdx.x == 0) g_bsum[blockIdx.x] = sh[0];
}

__global__ void k_scan2() {   // 1 block, 512 threads, Hillis-Steele inclusive
    __shared__ int sh[512];
    int t = threadIdx.x;
    int v0 = (t < SCAN_B) ? g_bsum[t] : 0;
    sh[t] = v0;
    __syncthreads();
    for (int d = 1; d < 512; d <<= 1) {
        int v = (t >= d) ? sh[t - d] : 0;
        __syncthreads();
        sh[t] += v;
        __syncthreads();
    }
    if (t < SCAN_B) g_bpre[t] = sh[t] - v0;   // exclusive prefix
}

__global__ void __launch_bounds__(256) k_scan3() {
    __shared__ int sh[256];
    int idx = blockIdx.x * 256 + threadIdx.x;
    int c = (idx < V_N) ? g_cnt[idx] : 0;
    sh[threadIdx.x] = c;
    __syncthreads();
    for (int d = 1; d < 256; d <<= 1) {
        int v = (threadIdx.x >= d) ? sh[threadIdx.x - d] : 0;
        __syncthreads();
        sh[threadIdx.x] += v;
        __syncthreads();
    }
    if (idx < V_N) {
        int off = g_bpre[blockIdx.x] + sh[threadIdx.x] - c;   // exclusive
        g_off[idx] = off;
        if (idx == V_N - 1) g_off[V_N] = off + c;
    }
}

__global__ void __launch_bounds__(256) k_slot_assign() {
    int e = blockIdx.x * 256 + threadIdx.x;
    if (e >= E_N) return;
    int d = g_dst[e];
    if (d < V_N) {
        int slot = g_off[d] + atomicAdd(&g_cursor[d], 1);
        g_slot[e] = slot;
        g_slotsrc[slot] = g_src[e];
    } else {
        g_slot[e] = -1;
    }
}

// P and Q: [100000 x 64] @ [64 x 128] GEMM, register-blocked, packed f32x2 FMA.
// Block = 256 threads handles 128 nodes. Thread tile = 8 nodes x 8 outputs
// (= 8n x 4 f32x2-pairs). FFMA-3reg rt_SMSP=2 was the ceiling; FMA2 halves
// the instruction count at identical rounding.
__global__ void __launch_bounds__(256) k_nodepre(const float* __restrict__ feat,
                                                 const float* __restrict__ Wxi) {
    __shared__ float fs[128 * 64];   // node-major staged features
    __shared__ float ws[64 * 128];   // ws[k][o]: o<64 -> W_node col k, o>=64 -> W_neis col k
    int tid = threadIdx.x;

    for (int idx = tid; idx < 64 * 128; idx += 256) {
        int k = idx >> 7, o = idx & 127;
        ws[idx] = Wxi[(o & 63) * 138 + ((o >> 6) << 6) + k];
    }

    int nodeBase = blockIdx.x * 128;
    const float4* f4 = reinterpret_cast<const float4*>(feat) + (size_t)nodeBase * 16;
    float4* fs4 = reinterpret_cast<float4*>(fs);
    #pragma unroll
    for (int j = 0; j < 8; j++) {
        int g = j * 256 + tid;
        if (nodeBase + (g >> 4) < V_N) fs4[g] = f4[g];
    }
    __syncthreads();

    int og = tid & 15;   // 16 output-groups x 8 outputs
    int ng = tid >> 4;   // 16 node-groups x 8 nodes

    u64 acc[8][4];
    #pragma unroll
    for (int n = 0; n < 8; n++)
        #pragma unroll
        for (int j = 0; j < 4; j++) acc[n][j] = 0ull;   // bits of (0.f, 0.f)

    const float* wp = ws + og * 8;
    const float* fp = fs + ng * 8 * 64;

    #pragma unroll 4
    for (int k = 0; k < 64; k++) {
        ulonglong2 wa = *reinterpret_cast<const ulonglong2*>(wp + k * 128);      // (w0,w1),(w2,w3)
        ulonglong2 wb = *reinterpret_cast<const ulonglong2*>(wp + k * 128 + 4);  // (w4,w5),(w6,w7)
        #pragma unroll
        for (int n = 0; n < 8; n++) {
            u64 ff = pack2(fp[n * 64 + k]);
            fma2(acc[n][0], ff, wa.x);
            fma2(acc[n][1], ff, wa.y);
            fma2(acc[n][2], ff, wb.x);
            fma2(acc[n][3], ff, wb.y);
        }
    }

    #pragma unroll
    for (int n = 0; n < 8; n++) {
        int node = nodeBase + ng * 8 + n;
        if (node >= V_N) continue;
        float* outp = (og < 8) ? (g_P + (size_t)node * 64 + og * 8)
                               : (g_Q + (size_t)node * 64 + (og - 8) * 8);
        *reinterpret_cast<ulonglong2*>(outp)     = make_ulonglong2(acc[n][0], acc[n][1]);
        *reinterpret_cast<ulonglong2*>(outp + 4) = make_ulonglong2(acc[n][2], acc[n][3]);
    }
}

// R[v][s] = tanh(feat[v] . W_rou[s] + b_rou[s]) with PRECISE tanh (only 800k values)
__global__ void __launch_bounds__(256) k_rou(const float* __restrict__ feat,
                                             const float* __restrict__ Wr,
                                             const float* __restrict__ br) {
    __shared__ float Ws[8][65];
    __shared__ float bs[8];
    int tid = threadIdx.x;
    for (int idx = tid; idx < 512; idx += 256) Ws[idx >> 6][idx & 63] = Wr[idx];
    if (tid < 8) bs[tid] = br[tid];
    __syncthreads();
    int g = blockIdx.x * 256 + tid;
    int v = g >> 3, s = g & 7;
    if (v >= V_N) return;
    const float* fr = feat + (size_t)v * 64;
    float acc = bs[s];
    #pragma unroll 8
    for (int i = 0; i < 64; i++) acc += __ldg(fr + i) * Ws[s][i];
    g_R[g] = tanhf(acc);
}

__global__ void __launch_bounds__(256) k_b2() {
    int g = blockIdx.x * 256 + threadIdx.x;
    if (g >= V_N * 8) return;
    int n = g >> 3, s = g & 7;
    g_B2[g] = (n >= 1) ? (float)g_cnt[n] * g_R[(n - 1) * 8 + s] : 0.f;
}

__global__ void __launch_bounds__(256) k_copyB2HA() {
    int g = blockIdx.x * 256 + threadIdx.x;
    if (g < V_N * 2)
        reinterpret_cast<float4*>(g_HA)[g] = reinterpret_cast<const float4*>(g_B2)[g];
}

// Per-edge A matrices (8 lanes/edge, lane i = row i), written into dst-sorted
// slot layout (row-major 128B/edge). FUSED STEP 1: the fp32 rows in registers
// are dotted with Hinit[src] and quad-shuffled into two red.v4 on g_HA.
__global__ void __launch_bounds__(256) k_aphase(const int* __restrict__ et_in,
                                                const float* __restrict__ dg_in,
                                                const float* __restrict__ Wxi,
                                                const float* __restrict__ bxi,
                                                const float* __restrict__ Hinit) {
    __shared__ float Cs[640];   // C[t][o] = Wxi[o][128+t] + bxi[o]
    for (int idx = threadIdx.x; idx < 640; idx += 256) {
        int t = idx >> 6, o = idx & 63;
        Cs[idx] = Wxi[o * 138 + 128 + t] + bxi[o];
    }
    __syncthreads();

    int g = blockIdx.x * 256 + threadIdx.x;   // grid = E*8/256 exactly
    int e = g >> 3, i = g & 7;
    int src  = g_src[e];
    int dseg = g_dst[e];
    int dv   = dseg - 1;                      // 0-indexed dst node for Q gather
    int et   = et_in[e] - 1;
    float s  = 0.1125f / dg_in[e];            // (MU/S)/deg

    const float4* Pp = reinterpret_cast<const float4*>(g_P + (size_t)src * 64 + i * 8);
    const float4* Qp = reinterpret_cast<const float4*>(g_Q + (size_t)dv * 64 + i * 8);
    float4 p0 = Pp[0], p1 = Pp[1];
    float4 q0 = Qp[0], q1 = Qp[1];
    const float* c = Cs + et * 64 + i * 8;

    float a0 = tanh_fast(p0.x + q0.x + c[0]) * s;
    float a1 = tanh_fast(p0.y + q0.y + c[1]) * s;
    float a2 = tanh_fast(p0.z + q0.z + c[2]) * s;
    float a3 = tanh_fast(p0.w + q0.w + c[3]) * s;
    float a4 = tanh_fast(p1.x + q1.x + c[4]) * s;
    float a5 = tanh_fast(p1.y + q1.y + c[5]) * s;
    float a6 = tanh_fast(p1.z + q1.z + c[6]) * s;
    float a7 = tanh_fast(p1.w + q1.w + c[7]) * s;

    int slot = g_slot[e];
    if (slot >= 0) {
        union { uint4 u; __half2 h[4]; } pk;
        pk.h[0] = __floats2half2_rn(a0, a1);
        pk.h[1] = __floats2half2_rn(a2, a3);
        pk.h[2] = __floats2half2_rn(a4, a5);
        pk.h[3] = __floats2half2_rn(a6, a7);
        reinterpret_cast<uint4*>(g_A)[(size_t)slot * 8 + i] = pk.u;
    }

    // fused recurrence step 1 (fp32 A, pre-rounding)
    const float4* hp = reinterpret_cast<const float4*>(Hinit + (size_t)src * 8);
    float4 h0 = __ldg(hp), h1 = __ldg(hp + 1);
    float out = a0 * h0.x + a1 * h0.y + a2 * h0.z + a3 * h0.w
              + a4 * h1.x + a5 * h1.y + a6 * h1.z + a7 * h1.w;

    int lane = threadIdx.x & 31;
    int q4 = lane & ~3;
    float t0 = __shfl_sync(0xffffffffu, out, q4);
    float t1 = __shfl_sync(0xffffffffu, out, q4 + 1);
    float t2 = __shfl_sync(0xffffffffu, out, q4 + 2);
    float t3 = __shfl_sync(0xffffffffu, out, q4 + 3);
    if ((lane & 3) == 0 && dseg < V_N)
        red_v4(g_HA + (size_t)dseg * 8 + (lane & 4), t0, t1, t2, t3);
}

// Recurrence step via CSR: warp = 4 nodes x 8 lanes; lane i owns row i and
// accumulates over the node's contiguous slot range. No atomics; A reads are
// one 128B line per edge per 8-lane group; H loads broadcast within group.
__global__ void __launch_bounds__(256) k_scat2(int srcSel) {
    const float* Hs = (srcSel == 1) ? g_HA : g_HB;
    float* Hd       = (srcSel == 1) ? g_HB : g_HA;

    int g = blockIdx.x * 256 + threadIdx.x;   // grid = V_N*8/256 = 3125 exactly
    int n = g >> 3, i = g & 7;
    int s0 = g_off[n], s1 = g_off[n + 1];
    float acc = g_B2[n * 8 + i];

    const uint4* Ab = reinterpret_cast<const uint4*>(g_A);
    for (int s = s0; s < s1; s++) {
        int src = g_slotsrc[s];
        const float4* hp = reinterpret_cast<const float4*>(Hs + (size_t)src * 8);
        float4 h0 = __ldg(hp), h1 = __ldg(hp + 1);
        uint4 a = __ldg(Ab + (size_t)s * 8 + i);
        const __half2* hh = reinterpret_cast<const __half2*>(&a);
        float2 f0 = __half22float2(hh[0]);
        float2 f1 = __half22float2(hh[1]);
        float2 f2 = __half22float2(hh[2]);
        float2 f3 = __half22float2(hh[3]);
        acc += f0.x * h0.x + f0.y * h0.y + f1.x * h0.z + f1.y * h0.w
             + f2.x * h1.x + f2.y * h1.y + f3.x * h1.z + f3.y * h1.w;
    }
    Hd[(size_t)n * 8 + i] = acc;
}

__global__ void __launch_bounds__(256) k_logits(const float* __restrict__ W1,
                                                const float* __restrict__ b1) {
    __shared__ float red[256];
    int v = blockIdx.x * 256 + threadIdx.x;
    float l = -3.0e38f;
    if (v < V_N) {
        const float4* hp = reinterpret_cast<const float4*>(g_HB + (size_t)v * 8);
        float4 h0 = hp[0], h1 = hp[1];
        l = b1[0]
          + h0.x * W1[0] + h0.y * W1[1] + h0.z * W1[2] + h0.w * W1[3]
          + h1.x * W1[4] + h1.y * W1[5] + h1.z * W1[6] + h1.w * W1[7];
        g_logits[v] = l;
    }
    red[threadIdx.x] = l;
    __syncthreads();
    for (int s = 128; s > 0; s >>= 1) {
        if (threadIdx.x < s) red[threadIdx.x] = fmaxf(red[threadIdx.x], red[threadIdx.x + s]);
        __syncthreads();
    }
    if (threadIdx.x == 0) {
        int o = __float_as_int(red[0]);
        o = (o >= 0) ? o : (o ^ 0x7fffffff);  // order-preserving int encoding
        atomicMax(&g_maxI, o);
    }
}

__global__ void __launch_bounds__(256) k_expsum() {
    int v = blockIdx.x * 256 + threadIdx.x;
    float p = 0.f;
    float w[8];
    #pragma unroll
    for (int s = 0; s < 8; s++) w[s] = 0.f;
    if (v < V_N) {
        int o = g_maxI;
        float m = (o >= 0) ? __int_as_float(o) : __int_as_float(o ^ 0x7fffffff);
        p = __expf(g_logits[v] - m);
        const float4* hp = reinterpret_cast<const float4*>(g_HB + (size_t)v * 8);
        float4 h0 = hp[0], h1 = hp[1];
        w[0] = p * h0.x; w[1] = p * h0.y; w[2] = p * h0.z; w[3] = p * h0.w;
        w[4] = p * h1.x; w[5] = p * h1.y; w[6] = p * h1.z; w[7] = p * h1.w;
    }
    #pragma unroll
    for (int d = 16; d > 0; d >>= 1) {
        p += __shfl_down_sync(0xffffffffu, p, d);
        #pragma unroll
        for (int s = 0; s < 8; s++) w[s] += __shfl_down_sync(0xffffffffu, w[s], d);
    }
    if ((threadIdx.x & 31) == 0) {
        atomicAdd(&g_sumExp, (double)p);
        #pragma unroll
        for (int s = 0; s < 8; s++) atomicAdd(&g_wsum[s], (double)w[s]);
    }
}

__global__ void k_fin(float* out) {
    int s = threadIdx.x;
    if (s < 8) out[s] = tanhf((float)(g_wsum[s] / g_sumExp));
}

// ---------------- launch ----------------
extern "C" void kernel_launch(void* const* d_in, const int* in_sizes, int n_in,
                              void* d_out, int out_size) {
    const float* feat  = (const float*)d_in[0];
    const void*  xn    = d_in[1];
    const void*  xs    = d_in[2];
    const int*   et    = (const int*)d_in[3];
    const float* dg    = (const float*)d_in[4];
    const float* Hinit = (const float*)d_in[5];
    const float* Wxi   = (const float*)d_in[6];
    const float* bxi   = (const float*)d_in[7];
    const float* Wr    = (const float*)d_in[8];
    const float* br    = (const float*)d_in[9];
    const float* W1    = (const float*)d_in[10];
    const float* b1    = (const float*)d_in[11];
    float* out = (float*)d_out;

    k_zero<<<(V_N + 255) / 256, 256>>>();
    k_detect<<<1, 32>>>(xn);
    k_prep<<<E_N / 256, 256>>>(xn, xs);

    // CSR build (counting sort by dst segment)
    k_scan1<<<SCAN_B, 256>>>();
    k_scan2<<<1, 512>>>();
    k_scan3<<<SCAN_B, 256>>>();
    k_slot_assign<<<E_N / 256, 256>>>();

    k_nodepre<<<(V_N + 127) / 128, 256>>>(feat, Wxi);
    k_rou<<<(V_N * 8 + 255) / 256, 256>>>(feat, Wr, br);
    k_b2<<<(V_N * 8 + 255) / 256, 256>>>();

    // step 1 fused into aphase: HA = B2 + sum_e A_e @ Hinit[src_e]
    k_copyB2HA<<<(V_N * 2 + 255) / 256, 256>>>();
    k_aphase<<<(E_N * 8) / 256, 256>>>(et, dg, Wxi, bxi, Hinit);

    // steps 2-4 via CSR, no atomics: HA->HB->HA->HB
    k_scat2<<<(V_N * 8) / 256, 256>>>(1);
    k_scat2<<<(V_N * 8) / 256, 256>>>(2);
    k_scat2<<<(V_N * 8) / 256, 256>>>(1);
    // final H in g_HB

    k_logits<<<(V_N + 255) / 256, 256>>>(W1, b1);
    k_expsum<<<(V_N + 255) / 256, 256>>>();
    k_fin<<<1, 32>>>(out);
}

// round 11
// speedup vs baseline: 1.2353x; 1.2353x over previous
#include <cuda_runtime.h>
#include <cuda_fp16.h>

#define V_N 100000
#define E_N 1600000

typedef unsigned long long u64;

// ---------------- static device scratch (no allocations allowed) ----------------
__device__ __half g_A[(size_t)E_N * 64];   // 204.8 MB, tiled layout: [e/256][row i][e%256] as uint4(8 halves)
__device__ float  g_P[V_N * 64];           // feat @ Wxi[:, 0:64]^T
__device__ float  g_Q[V_N * 64];           // feat @ Wxi[:, 64:128]^T
__device__ float  g_R[V_N * 8];            // tanh(feat @ W_rou^T + b_rou)
__device__ float  g_B2[V_N * 8];           // per-step init: cnt[n] * R[n-1]
__device__ float  g_HA[V_N * 8];
__device__ float  g_HB[V_N * 8];
__device__ int    g_src[E_N];              // X_Node - 1
__device__ int    g_dst[E_N];              // raw X_Neis (1-indexed segment id)
__device__ int    g_cnt[V_N];
__device__ float  g_logits[V_N];
__device__ int    g_is64;
__device__ int    g_maxI;
__device__ double g_sumExp;
__device__ double g_wsum[8];

// ---------------- helpers ----------------
__device__ __forceinline__ float tanh_fast(float x) {
    x = fminf(fmaxf(x, -9.f), 9.f);
    float t = __expf(2.f * x);
    return __fdividef(t - 1.f, t + 1.f);
}

__device__ __forceinline__ void red_v4(float* p, float a, float b, float c, float d) {
    asm volatile("red.global.add.v4.f32 [%0], {%1, %2, %3, %4};"
                 :: "l"(p), "f"(a), "f"(b), "f"(c), "f"(d) : "memory");
}

// packed fp32x2 FMA (Blackwell; .rn lanewise, bit-identical to scalar FFMA)
__device__ __forceinline__ void fma2(u64& d, u64 a, u64 b) {
    asm("fma.rn.f32x2 %0, %1, %2, %0;" : "+l"(d) : "l"(a), "l"(b));
}
__device__ __forceinline__ u64 pack2(float f) {
    u64 r;
    asm("mov.b64 %0, {%1, %1};" : "=l"(r) : "r"(__float_as_uint(f)));
    return r;
}

// ---------------- kernels ----------------
__global__ void k_zero() {
    int i = blockIdx.x * blockDim.x + threadIdx.x;
    if (i < V_N) g_cnt[i] = 0;
    if (i == 0) {
        g_maxI = (int)0x80000000;
        g_sumExp = 0.0;
        #pragma unroll
        for (int s = 0; s < 8; s++) g_wsum[s] = 0.0;
    }
}

// Detect int64 vs int32 index arrays: values are in [1, V] (never 0), so the
// high dword of an int64 little-endian pair is 0 iff the data is int64.
__global__ void k_detect(const void* xn) {
    if (blockIdx.x == 0 && threadIdx.x == 0) {
        const int2* p = (const int2*)xn;
        int ok = 1;
        for (int k = 0; k < 64; k++) if (p[k].y != 0) ok = 0;
        g_is64 = ok;
    }
}

__global__ void __launch_bounds__(256) k_prep(const void* xn, const void* xs) {
    int e = blockIdx.x * 256 + threadIdx.x;
    if (e >= E_N) return;
    long long a, b;
    if (g_is64) {
        a = ((const long long*)xn)[e];
        b = ((const long long*)xs)[e];
    } else {
        a = ((const int*)xn)[e];
        b = ((const int*)xs)[e];
    }
    g_src[e] = (int)(a - 1);
    int d = (int)b;
    g_dst[e] = d;
    if (d < V_N) atomicAdd(&g_cnt[d], 1);   // segment id == V is dropped
}

// P and Q: [100000 x 64] @ [64 x 128] GEMM, register-blocked, packed f32x2 FMA.
// Block = 256 threads handles 128 nodes. Thread tile = 8 nodes x 8 outputs
// (= 8n x 4 f32x2-pairs). FFMA-3reg rt_SMSP=2 was the ceiling; FMA2 halves
// the instruction count at identical rounding.
__global__ void __launch_bounds__(256) k_nodepre(const float* __restrict__ feat,
                                                 const float* __restrict__ Wxi) {
    __shared__ float fs[128 * 64];   // node-major staged features
    __shared__ float ws[64 * 128];   // ws[k][o]: o<64 -> W_node col k, o>=64 -> W_neis col k
    int tid = threadIdx.x;

    for (int idx = tid; idx < 64 * 128; idx += 256) {
        int k = idx >> 7, o = idx & 127;
        ws[idx] = Wxi[(o & 63) * 138 + ((o >> 6) << 6) + k];
    }

    int nodeBase = blockIdx.x * 128;
    const float4* f4 = reinterpret_cast<const float4*>(feat) + (size_t)nodeBase * 16;
    float4* fs4 = reinterpret_cast<float4*>(fs);
    #pragma unroll
    for (int j = 0; j < 8; j++) {
        int g = j * 256 + tid;
        if (nodeBase + (g >> 4) < V_N) fs4[g] = f4[g];
    }
    __syncthreads();

    int og = tid & 15;   // 16 output-groups x 8 outputs
    int ng = tid >> 4;   // 16 node-groups x 8 nodes

    u64 acc[8][4];
    #pragma unroll
    for (int n = 0; n < 8; n++)
        #pragma unroll
        for (int j = 0; j < 4; j++) acc[n][j] = 0ull;   // bits of (0.f, 0.f)

    const float* wp = ws + og * 8;
    const float* fp = fs + ng * 8 * 64;

    #pragma unroll 4
    for (int k = 0; k < 64; k++) {
        ulonglong2 wa = *reinterpret_cast<const ulonglong2*>(wp + k * 128);      // (w0,w1),(w2,w3)
        ulonglong2 wb = *reinterpret_cast<const ulonglong2*>(wp + k * 128 + 4);  // (w4,w5),(w6,w7)
        #pragma unroll
        for (int n = 0; n < 8; n++) {
            u64 ff = pack2(fp[n * 64 + k]);
            fma2(acc[n][0], ff, wa.x);
            fma2(acc[n][1], ff, wa.y);
            fma2(acc[n][2], ff, wb.x);
            fma2(acc[n][3], ff, wb.y);
        }
    }

    #pragma unroll
    for (int n = 0; n < 8; n++) {
        int node = nodeBase + ng * 8 + n;
        if (node >= V_N) continue;
        float* outp = (og < 8) ? (g_P + (size_t)node * 64 + og * 8)
                               : (g_Q + (size_t)node * 64 + (og - 8) * 8);
        *reinterpret_cast<ulonglong2*>(outp)     = make_ulonglong2(acc[n][0], acc[n][1]);
        *reinterpret_cast<ulonglong2*>(outp + 4) = make_ulonglong2(acc[n][2], acc[n][3]);
    }
}

// R[v][s] = tanh(feat[v] . W_rou[s] + b_rou[s]) with PRECISE tanh (only 800k values)
__global__ void __launch_bounds__(256) k_rou(const float* __restrict__ feat,
                                             const float* __restrict__ Wr,
                                             const float* __restrict__ br) {
    __shared__ float Ws[8][65];
    __shared__ float bs[8];
    int tid = threadIdx.x;
    for (int idx = tid; idx < 512; idx += 256) Ws[idx >> 6][idx & 63] = Wr[idx];
    if (tid < 8) bs[tid] = br[tid];
    __syncthreads();
    int g = blockIdx.x * 256 + tid;
    int v = g >> 3, s = g & 7;
    if (v >= V_N) return;
    const float* fr = feat + (size_t)v * 64;
    float acc = bs[s];
    #pragma unroll 8
    for (int i = 0; i < 64; i++) acc += __ldg(fr + i) * Ws[s][i];
    g_R[g] = tanhf(acc);
}

__global__ void __launch_bounds__(256) k_b2() {
    int g = blockIdx.x * 256 + threadIdx.x;
    if (g >= V_N * 8) return;
    int n = g >> 3, s = g & 7;
    g_B2[g] = (n >= 1) ? (float)g_cnt[n] * g_R[(n - 1) * 8 + s] : 0.f;
}

__global__ void __launch_bounds__(256) k_copy(int dstSel) {
    float* dst = (dstSel == 1) ? g_HA : g_HB;
    int g = blockIdx.x * 256 + threadIdx.x;
    if (g < V_N * 2) reinterpret_cast<float4*>(dst)[g] = reinterpret_cast<const float4*>(g_B2)[g];
}

// Per-edge A matrices (8 lanes/edge, lane i = row i), written in the tiled
// scatter-friendly layout. FUSED STEP 1: the fp32 rows still in registers are
// dotted with Hinit[src] and quad-shuffled into two red.v4 onto g_HA
// (pre-initialized with B2), eliminating one full 205MB A-read pass.
__global__ void __launch_bounds__(256) k_aphase(const int* __restrict__ et_in,
                                                const float* __restrict__ dg_in,
                                                const float* __restrict__ Wxi,
                                                const float* __restrict__ bxi,
                                                const float* __restrict__ Hinit) {
    __shared__ float Cs[640];   // C[t][o] = Wxi[o][128+t] + bxi[o]
    for (int idx = threadIdx.x; idx < 640; idx += 256) {
        int t = idx >> 6, o = idx & 63;
        Cs[idx] = Wxi[o * 138 + 128 + t] + bxi[o];
    }
    __syncthreads();

    int g = blockIdx.x * 256 + threadIdx.x;   // grid = E*8/256 exactly
    int e = g >> 3, i = g & 7;
    int src  = g_src[e];
    int dseg = g_dst[e];
    int dv   = dseg - 1;                      // 0-indexed dst node for Q gather
    int et   = et_in[e] - 1;
    float s  = 0.1125f / dg_in[e];            // (MU/S)/deg

    const float4* Pp = reinterpret_cast<const float4*>(g_P + (size_t)src * 64 + i * 8);
    const float4* Qp = reinterpret_cast<const float4*>(g_Q + (size_t)dv * 64 + i * 8);
    float4 p0 = Pp[0], p1 = Pp[1];
    float4 q0 = Qp[0], q1 = Qp[1];
    const float* c = Cs + et * 64 + i * 8;

    float a0 = tanh_fast(p0.x + q0.x + c[0]) * s;
    float a1 = tanh_fast(p0.y + q0.y + c[1]) * s;
    float a2 = tanh_fast(p0.z + q0.z + c[2]) * s;
    float a3 = tanh_fast(p0.w + q0.w + c[3]) * s;
    float a4 = tanh_fast(p1.x + q1.x + c[4]) * s;
    float a5 = tanh_fast(p1.y + q1.y + c[5]) * s;
    float a6 = tanh_fast(p1.z + q1.z + c[6]) * s;
    float a7 = tanh_fast(p1.w + q1.w + c[7]) * s;

    union { uint4 u; __half2 h[4]; } pk;
    pk.h[0] = __floats2half2_rn(a0, a1);
    pk.h[1] = __floats2half2_rn(a2, a3);
    pk.h[2] = __floats2half2_rn(a4, a5);
    pk.h[3] = __floats2half2_rn(a6, a7);
    size_t oi = (size_t)(e >> 8) * 2048 + (size_t)i * 256 + (e & 255);
    reinterpret_cast<uint4*>(g_A)[oi] = pk.u;

    // fused recurrence step 1 (fp32 A, pre-rounding)
    const float4* hp = reinterpret_cast<const float4*>(Hinit + (size_t)src * 8);
    float4 h0 = __ldg(hp), h1 = __ldg(hp + 1);
    float out = a0 * h0.x + a1 * h0.y + a2 * h0.z + a3 * h0.w
              + a4 * h1.x + a5 * h1.y + a6 * h1.z + a7 * h1.w;

    int lane = threadIdx.x & 31;
    int q4 = lane & ~3;
    float t0 = __shfl_sync(0xffffffffu, out, q4);
    float t1 = __shfl_sync(0xffffffffu, out, q4 + 1);
    float t2 = __shfl_sync(0xffffffffu, out, q4 + 2);
    float t3 = __shfl_sync(0xffffffffu, out, q4 + 3);
    if ((lane & 3) == 0 && dseg < V_N)
        red_v4(g_HA + (size_t)dseg * 8 + (lane & 4), t0, t1, t2, t3);
}

// One recurrence step: per edge, out = A_e @ H[src_e], vector-reduced into Hdst[X_Neis].
// 8 front-batched independent A loads (MLP=8), coalesced 512B/warp per row.
__global__ void __launch_bounds__(256) k_scatter(int srcSel, int dstSel) {
    const float* Hs = (srcSel == 1) ? g_HA : g_HB;
    float* Hd       = (dstSel == 1) ? g_HA : g_HB;

    int e = blockIdx.x * 256 + threadIdx.x;   // grid = E/256 exactly
    int src  = g_src[e];
    int dseg = g_dst[e];

    const float4* hp = reinterpret_cast<const float4*>(Hs + (size_t)src * 8);
    float4 h0 = __ldg(hp);
    float4 h1 = __ldg(hp + 1);

    const uint4* Ab = reinterpret_cast<const uint4*>(g_A)
                      + (size_t)blockIdx.x * 2048 + threadIdx.x;
    float out[8];
    #pragma unroll
    for (int i = 0; i < 8; i++) {
        uint4 a = __ldg(Ab + i * 256);        // row i of this edge's 8x8, coalesced across warp
        const __half2* hh = reinterpret_cast<const __half2*>(&a);
        float2 f0 = __half22float2(hh[0]);
        float2 f1 = __half22float2(hh[1]);
        float2 f2 = __half22float2(hh[2]);
        float2 f3 = __half22float2(hh[3]);
        out[i] = f0.x * h0.x + f0.y * h0.y + f1.x * h0.z + f1.y * h0.w
               + f2.x * h1.x + f2.y * h1.y + f3.x * h1.z + f3.y * h1.w;
    }
    if (dseg < V_N) {
        float* p = Hd + (size_t)dseg * 8;
        red_v4(p,     out[0], out[1], out[2], out[3]);
        red_v4(p + 4, out[4], out[5], out[6], out[7]);
    }
}

__global__ void __launch_bounds__(256) k_logits(const float* __restrict__ W1,
                                                const float* __restrict__ b1) {
    __shared__ float red[256];
    int v = blockIdx.x * 256 + threadIdx.x;
    float l = -3.0e38f;
    if (v < V_N) {
        const float4* hp = reinterpret_cast<const float4*>(g_HB + (size_t)v * 8);
        float4 h0 = hp[0], h1 = hp[1];
        l = b1[0]
          + h0.x * W1[0] + h0.y * W1[1] + h0.z * W1[2] + h0.w * W1[3]
          + h1.x * W1[4] + h1.y * W1[5] + h1.z * W1[6] + h1.w * W1[7];
        g_logits[v] = l;
    }
    red[threadIdx.x] = l;
    __syncthreads();
    for (int s = 128; s > 0; s >>= 1) {
        if (threadIdx.x < s) red[threadIdx.x] = fmaxf(red[threadIdx.x], red[threadIdx.x + s]);
        __syncthreads();
    }
    if (threadIdx.x == 0) {
        int o = __float_as_int(red[0]);
        o = (o >= 0) ? o : (o ^ 0x7fffffff);  // order-preserving int encoding
        atomicMax(&g_maxI, o);
    }
}

__global__ void __launch_bounds__(256) k_expsum() {
    int v = blockIdx.x * 256 + threadIdx.x;
    float p = 0.f;
    float w[8];
    #pragma unroll
    for (int s = 0; s < 8; s++) w[s] = 0.f;
    if (v < V_N) {
        int o = g_maxI;
        float m = (o >= 0) ? __int_as_float(o) : __int_as_float(o ^ 0x7fffffff);
        p = __expf(g_logits[v] - m);
        const float4* hp = reinterpret_cast<const float4*>(g_HB + (size_t)v * 8);
        float4 h0 = hp[0], h1 = hp[1];
        w[0] = p * h0.x; w[1] = p * h0.y; w[2] = p * h0.z; w[3] = p * h0.w;
        w[4] = p * h1.x; w[5] = p * h1.y; w[6] = p * h1.z; w[7] = p * h1.w;
    }
    #pragma unroll
    for (int d = 16; d > 0; d >>= 1) {
        p += __shfl_down_sync(0xffffffffu, p, d);
        #pragma unroll
        for (int s = 0; s < 8; s++) w[s] += __shfl_down_sync(0xffffffffu, w[s], d);
    }
    if ((threadIdx.x & 31) == 0) {
        atomicAdd(&g_sumExp, (double)p);
        #pragma unroll
        for (int s = 0; s < 8; s++) atomicAdd(&g_wsum[s], (double)w[s]);
    }
}

__global__ void k_fin(float* out) {
    int s = threadIdx.x;
    if (s < 8) out[s] = tanhf((float)(g_wsum[s] / g_sumExp));
}

// ---------------- launch ----------------
extern "C" void kernel_launch(void* const* d_in, const int* in_sizes, int n_in,
                              void* d_out, int out_size) {
    const float* feat  = (const float*)d_in[0];
    const void*  xn    = d_in[1];
    const void*  xs    = d_in[2];
    const int*   et    = (const int*)d_in[3];
    const float* dg    = (const float*)d_in[4];
    const float* Hinit = (const float*)d_in[5];
    const float* Wxi   = (const float*)d_in[6];
    const float* bxi   = (const float*)d_in[7];
    const float* Wr    = (const float*)d_in[8];
    const float* br    = (const float*)d_in[9];
    const float* W1    = (const float*)d_in[10];
    const float* b1    = (const float*)d_in[11];
    float* out = (float*)d_out;

    k_zero<<<(V_N + 255) / 256, 256>>>();
    k_detect<<<1, 32>>>(xn);
    k_prep<<<E_N / 256, 256>>>(xn, xs);
    k_nodepre<<<(V_N + 127) / 128, 256>>>(feat, Wxi);
    k_rou<<<(V_N * 8 + 255) / 256, 256>>>(feat, Wr, br);
    k_b2<<<(V_N * 8 + 255) / 256, 256>>>();

    // step 1 fused into aphase: HA = B2 + sum_e A_e @ Hinit[src_e]
    k_copy<<<(V_N * 2 + 255) / 256, 256>>>(1);
    k_aphase<<<(E_N * 8) / 256, 256>>>(et, dg, Wxi, bxi, Hinit);

    // steps 2-4, ping-ponging HA/HB, atomic scatter with tiled A
    k_copy<<<(V_N * 2 + 255) / 256, 256>>>(2);
    k_scatter<<<E_N / 256, 256>>>(1, 2);
    k_copy<<<(V_N * 2 + 255) / 256, 256>>>(1);
    k_scatter<<<E_N / 256, 256>>>(2, 1);
    k_copy<<<(V_N * 2 + 255) / 256, 256>>>(2);
    k_scatter<<<E_N / 256, 256>>>(1, 2);
    // final H in g_HB

    k_logits<<<(V_N + 255) / 256, 256>>>(W1, b1);
    k_expsum<<<(V_N + 255) / 256, 256>>>();
    k_fin<<<1, 32>>>(out);
}